// round 5
// baseline (speedup 1.0000x reference)
#include <cuda_runtime.h>
#include <cuda_bf16.h>
#include <cstdint>

#define D 128
#define MAX_N 100000
#define MAX_E 1600000
#define SCAN_BLK 512
#define KS 136                      // padded smem row stride (bf16 elems), 272B = 16B-aligned

// ---------------- device-global scratch (allocation-free rule) ----------------
__device__ float g_hop1[(size_t)MAX_N * D];
__device__ float g_hop2[(size_t)MAX_N * D];
__device__ int   g_cnt[MAX_N];
__device__ int   g_rs[MAX_N + 1];
__device__ int   g_cursor[MAX_N];
__device__ int   g_bsum[1024];
__device__ int   g_ccol[MAX_E];
__device__ float g_cval[MAX_E];
__device__ __nv_bfloat16 g_wt_hi[3][D * D];   // W^T split, hi part  (wt[n][k])
__device__ __nv_bfloat16 g_wt_lo[3][D * D];   // W^T split, lo part

__device__ __forceinline__ uint32_t smem_u32(const void* p) {
    uint32_t a;
    asm("{ .reg .u64 t; cvta.to.shared.u64 t, %1; cvt.u32.u64 %0, t; }" : "=r"(a) : "l"(p));
    return a;
}
__device__ __forceinline__ void ldsm4(uint32_t& r0, uint32_t& r1, uint32_t& r2,
                                      uint32_t& r3, uint32_t addr) {
    asm volatile("ldmatrix.sync.aligned.m8n8.x4.shared.b16 {%0,%1,%2,%3}, [%4];"
                 : "=r"(r0), "=r"(r1), "=r"(r2), "=r"(r3) : "r"(addr));
}
__device__ __forceinline__ void mma16816(float* c, uint32_t a0, uint32_t a1,
                                         uint32_t a2, uint32_t a3,
                                         uint32_t b0, uint32_t b1) {
    asm volatile("mma.sync.aligned.m16n8k16.row.col.f32.bf16.bf16.f32 "
                 "{%0,%1,%2,%3}, {%4,%5,%6,%7}, {%8,%9}, {%0,%1,%2,%3};"
                 : "+f"(c[0]), "+f"(c[1]), "+f"(c[2]), "+f"(c[3])
                 : "r"(a0), "r"(a1), "r"(a2), "r"(a3), "r"(b0), "r"(b1));
}

// ---------------------------------------------------------------------------
// CSR construction (unchanged from R3)
// ---------------------------------------------------------------------------
__global__ void hist_kernel(const int* __restrict__ row, int n_edges, int* __restrict__ cnt) {
    int e = blockIdx.x * blockDim.x + threadIdx.x;
    if (e < n_edges) atomicAdd(&cnt[row[e]], 1);
}
__global__ void scan_block_kernel(const int* __restrict__ cnt, int* __restrict__ rs,
                                  int* __restrict__ bsum, int n) {
    __shared__ int sh[SCAN_BLK];
    int i = blockIdx.x * SCAN_BLK + threadIdx.x;
    int v = (i < n) ? cnt[i] : 0;
    sh[threadIdx.x] = v;
    __syncthreads();
    #pragma unroll
    for (int o = 1; o < SCAN_BLK; o <<= 1) {
        int t = (threadIdx.x >= o) ? sh[threadIdx.x - o] : 0;
        __syncthreads();
        sh[threadIdx.x] += t;
        __syncthreads();
    }
    int incl = sh[threadIdx.x];
    if (i < n) rs[i] = incl - v;
    if (threadIdx.x == SCAN_BLK - 1) bsum[blockIdx.x] = incl;
}
__global__ void scan_bsum_kernel(int* __restrict__ bsum, int nb) {
    __shared__ int sh[1024];
    int v = (threadIdx.x < nb) ? bsum[threadIdx.x] : 0;
    sh[threadIdx.x] = v;
    __syncthreads();
    #pragma unroll
    for (int o = 1; o < 1024; o <<= 1) {
        int t = (threadIdx.x >= o) ? sh[threadIdx.x - o] : 0;
        __syncthreads();
        sh[threadIdx.x] += t;
        __syncthreads();
    }
    if (threadIdx.x < nb) bsum[threadIdx.x] = sh[threadIdx.x] - v;
}
__global__ void scan_add_kernel(int* __restrict__ rs, const int* __restrict__ bsum,
                                int* __restrict__ cursor, int n, int total) {
    int i = blockIdx.x * blockDim.x + threadIdx.x;
    if (i < n) {
        int v = rs[i] + bsum[i >> 9];
        rs[i] = v;
        cursor[i] = v;
    }
    if (i == n) rs[n] = total;
}
__global__ void scatter_kernel(const int* __restrict__ row, const int* __restrict__ col,
                               const float* __restrict__ vals, int n_edges,
                               int* __restrict__ cursor, int* __restrict__ ccol,
                               float* __restrict__ cval) {
    int e = blockIdx.x * blockDim.x + threadIdx.x;
    if (e >= n_edges) return;
    int r = row[e];
    int p = atomicAdd(&cursor[r], 1);
    ccol[p] = col[e];
    cval[p] = vals[e];
}

// ---------------------------------------------------------------------------
// Gather SpMM (unchanged from R3)
// ---------------------------------------------------------------------------
__global__ void __launch_bounds__(256)
spmm_gather_kernel(const float* __restrict__ x, float* __restrict__ y,
                   const int* __restrict__ rs, const int* __restrict__ ccol,
                   const float* __restrict__ cval, int n_rows) {
    int w    = (blockIdx.x * blockDim.x + threadIdx.x) >> 5;
    int lane = threadIdx.x & 31;
    if (w >= n_rows) return;
    int s = __ldg(&rs[w]);
    int e = __ldg(&rs[w + 1]);
    float4 acc = make_float4(0.f, 0.f, 0.f, 0.f);
    int j = s;
    for (; j + 3 < e; j += 4) {
        int   c0 = __ldg(&ccol[j]),     c1 = __ldg(&ccol[j + 1]);
        int   c2 = __ldg(&ccol[j + 2]), c3 = __ldg(&ccol[j + 3]);
        float v0 = __ldg(&cval[j]),     v1 = __ldg(&cval[j + 1]);
        float v2 = __ldg(&cval[j + 2]), v3 = __ldg(&cval[j + 3]);
        float4 x0 = ((const float4*)x)[(size_t)c0 * 32 + lane];
        float4 x1 = ((const float4*)x)[(size_t)c1 * 32 + lane];
        float4 x2 = ((const float4*)x)[(size_t)c2 * 32 + lane];
        float4 x3 = ((const float4*)x)[(size_t)c3 * 32 + lane];
        acc.x = fmaf(v0, x0.x, fmaf(v1, x1.x, fmaf(v2, x2.x, fmaf(v3, x3.x, acc.x))));
        acc.y = fmaf(v0, x0.y, fmaf(v1, x1.y, fmaf(v2, x2.y, fmaf(v3, x3.y, acc.y))));
        acc.z = fmaf(v0, x0.z, fmaf(v1, x1.z, fmaf(v2, x2.z, fmaf(v3, x3.z, acc.z))));
        acc.w = fmaf(v0, x0.w, fmaf(v1, x1.w, fmaf(v2, x2.w, fmaf(v3, x3.w, acc.w))));
    }
    for (; j < e; j++) {
        int   c = __ldg(&ccol[j]);
        float v = __ldg(&cval[j]);
        float4 xv = ((const float4*)x)[(size_t)c * 32 + lane];
        acc.x = fmaf(v, xv.x, acc.x);
        acc.y = fmaf(v, xv.y, acc.y);
        acc.z = fmaf(v, xv.z, acc.z);
        acc.w = fmaf(v, xv.w, acc.w);
    }
    ((float4*)y)[(size_t)w * 32 + lane] = acc;
}

// ---------------------------------------------------------------------------
// W transpose + bf16 hi/lo split: WT_hi[n][k] + WT_lo[n][k] = W[k][n]
// ---------------------------------------------------------------------------
__global__ void wsplit_kernel(const float* __restrict__ W,
                              __nv_bfloat16* __restrict__ wt_hi,
                              __nv_bfloat16* __restrict__ wt_lo) {
    int idx = blockIdx.x * blockDim.x + threadIdx.x;   // 0..16383
    int k = idx >> 7, n = idx & 127;
    float a = W[idx];
    __nv_bfloat16 h = __float2bfloat16(a);
    float res = a - __bfloat162float(h);
    wt_hi[n * D + k] = h;
    wt_lo[n * D + k] = __float2bfloat16(res);
}

// ---------------------------------------------------------------------------
// mma.sync bf16 3-pass-split GEMM (128x128 tile) + bias + relu + row-norm.
// acc = Ah*Bh + Ah*Bl + Al*Bh in fp32 fragments.
// 8 warps, each owns 16 rows x 128 cols (16 n8-tiles).
// ---------------------------------------------------------------------------
#define TC_SMEM (4 * 128 * KS * 2)           // 139264 bytes

__global__ void __launch_bounds__(256)
gemm_mma_kernel(const float* __restrict__ V,
                const __nv_bfloat16* __restrict__ wt_hi,
                const __nv_bfloat16* __restrict__ wt_lo,
                const float* __restrict__ b,
                const float* __restrict__ off,
                const float* __restrict__ sc,
                float* __restrict__ out,
                int n_rows, int accumulate) {
    extern __shared__ __nv_bfloat16 sm[];
    __nv_bfloat16* Ah = sm;
    __nv_bfloat16* Al = Ah + 128 * KS;
    __nv_bfloat16* Bh = Al + 128 * KS;
    __nv_bfloat16* Bl = Bh + 128 * KS;

    const int tid  = threadIdx.x;
    const int wid  = tid >> 5;
    const int lane = tid & 31;
    const int row0 = blockIdx.x * 128;

    // ---- stage A: fp32 -> bf16 hi/lo into padded tiles ----
    const float4* Vf4 = (const float4*)V;
    for (int idx = tid; idx < 128 * 32; idx += 256) {
        int r = idx >> 5;
        int c4 = (idx & 31) << 2;
        float4 v = make_float4(0.f, 0.f, 0.f, 0.f);
        if (row0 + r < n_rows) v = Vf4[(size_t)(row0 + r) * 32 + (idx & 31)];

        __nv_bfloat16 h0 = __float2bfloat16(v.x);
        __nv_bfloat16 h1 = __float2bfloat16(v.y);
        __nv_bfloat16 h2 = __float2bfloat16(v.z);
        __nv_bfloat16 h3 = __float2bfloat16(v.w);
        __nv_bfloat16 l0 = __float2bfloat16(v.x - __bfloat162float(h0));
        __nv_bfloat16 l1 = __float2bfloat16(v.y - __bfloat162float(h1));
        __nv_bfloat16 l2 = __float2bfloat16(v.z - __bfloat162float(h2));
        __nv_bfloat16 l3 = __float2bfloat16(v.w - __bfloat162float(h3));

        uint2 hp, lp;
        hp.x = ((uint32_t)__bfloat16_as_ushort(h1) << 16) | __bfloat16_as_ushort(h0);
        hp.y = ((uint32_t)__bfloat16_as_ushort(h3) << 16) | __bfloat16_as_ushort(h2);
        lp.x = ((uint32_t)__bfloat16_as_ushort(l1) << 16) | __bfloat16_as_ushort(l0);
        lp.y = ((uint32_t)__bfloat16_as_ushort(l3) << 16) | __bfloat16_as_ushort(l2);

        *(uint2*)&Ah[r * KS + c4] = hp;
        *(uint2*)&Al[r * KS + c4] = lp;
    }
    // ---- stage B (pre-split W^T, row n of k) ----
    const uint2* bhg = (const uint2*)wt_hi;
    const uint2* blg = (const uint2*)wt_lo;
    for (int idx = tid; idx < 128 * 32; idx += 256) {
        int r = idx >> 5;
        int c4 = (idx & 31) << 2;
        *(uint2*)&Bh[r * KS + c4] = __ldg(&bhg[idx]);
        *(uint2*)&Bl[r * KS + c4] = __ldg(&blg[idx]);
    }
    __syncthreads();

    // ---- mainloop: 8 k-steps, 16 n-tiles, 3 passes ----
    float acc[16][4];
    #pragma unroll
    for (int j = 0; j < 16; j++)
        #pragma unroll
        for (int q = 0; q < 4; q++) acc[j][q] = 0.f;

    // A ldmatrix lane address: rows = wid*16 + (lane%16), k-half = lane/16
    const uint32_t Ah_u = smem_u32(Ah), Al_u = smem_u32(Al);
    const uint32_t Bh_u = smem_u32(Bh), Bl_u = smem_u32(Bl);
    const uint32_t a_lane_off = (uint32_t)((wid * 16 + (lane & 15)) * KS + (lane >> 4) * 8) * 2;
    // B ldmatrix lane pattern (covers 2 n8-tiles per x4)
    const int nb = (lane & 7) + ((lane >> 4) & 1) * 8;
    const int kb = ((lane >> 3) & 1) * 8;

    #pragma unroll
    for (int k0 = 0; k0 < 128; k0 += 16) {
        uint32_t ah0, ah1, ah2, ah3, al0, al1, al2, al3;
        ldsm4(ah0, ah1, ah2, ah3, Ah_u + a_lane_off + k0 * 2);
        ldsm4(al0, al1, al2, al3, Al_u + a_lane_off + k0 * 2);

        #pragma unroll
        for (int j = 0; j < 8; j++) {
            const uint32_t b_off = (uint32_t)((j * 16 + nb) * KS + k0 + kb) * 2;
            uint32_t bh0, bh1, bh2, bh3, bl0, bl1, bl2, bl3;
            ldsm4(bh0, bh1, bh2, bh3, Bh_u + b_off);
            ldsm4(bl0, bl1, bl2, bl3, Bl_u + b_off);

            mma16816(acc[2 * j],     ah0, ah1, ah2, ah3, bh0, bh1);
            mma16816(acc[2 * j + 1], ah0, ah1, ah2, ah3, bh2, bh3);
            mma16816(acc[2 * j],     ah0, ah1, ah2, ah3, bl0, bl1);
            mma16816(acc[2 * j + 1], ah0, ah1, ah2, ah3, bl2, bl3);
            mma16816(acc[2 * j],     al0, al1, al2, al3, bh0, bh1);
            mma16816(acc[2 * j + 1], al0, al1, al2, al3, bh2, bh3);
        }
    }

    // ---- epilogue: bias+relu, row moments (4-lane reduce), affine, store ----
    const int lrow  = lane >> 2;         // 0..7
    const int lcol2 = (lane & 3) * 2;
    float s0 = 0.f, sq0 = 0.f, s1 = 0.f, sq1 = 0.f;
    #pragma unroll
    for (int j = 0; j < 16; j++) {
        float2 bb = *(const float2*)&b[j * 8 + lcol2];
        float x0 = fmaxf(acc[j][0] + bb.x, 0.f);
        float x1 = fmaxf(acc[j][1] + bb.y, 0.f);
        float x2 = fmaxf(acc[j][2] + bb.x, 0.f);
        float x3 = fmaxf(acc[j][3] + bb.y, 0.f);
        acc[j][0] = x0; acc[j][1] = x1; acc[j][2] = x2; acc[j][3] = x3;
        s0 += x0 + x1; sq0 += x0 * x0 + x1 * x1;
        s1 += x2 + x3; sq1 += x2 * x2 + x3 * x3;
    }
    #pragma unroll
    for (int o = 1; o <= 2; o <<= 1) {
        s0  += __shfl_xor_sync(0xffffffffu, s0,  o);
        sq0 += __shfl_xor_sync(0xffffffffu, sq0, o);
        s1  += __shfl_xor_sync(0xffffffffu, s1,  o);
        sq1 += __shfl_xor_sync(0xffffffffu, sq1, o);
    }
    const float inv_d = 1.0f / 128.0f;
    float mean0 = s0 * inv_d, var0 = sq0 * inv_d - mean0 * mean0;
    float mean1 = s1 * inv_d, var1 = sq1 * inv_d - mean1 * mean1;
    float inv0 = rsqrtf(var0 + 1e-9f);
    float inv1 = rsqrtf(var1 + 1e-9f);

    const int r0 = row0 + wid * 16 + lrow;
    const int r1 = r0 + 8;
    #pragma unroll
    for (int j = 0; j < 16; j++) {
        float2 scv = *(const float2*)&sc[j * 8 + lcol2];
        float2 ofv = *(const float2*)&off[j * 8 + lcol2];
        if (r0 < n_rows) {
            float2* p = (float2*)&out[(size_t)r0 * D + j * 8 + lcol2];
            float2 res;
            res.x = scv.x * (acc[j][0] - mean0) * inv0 + ofv.x;
            res.y = scv.y * (acc[j][1] - mean0) * inv0 + ofv.y;
            if (accumulate) { float2 c = *p; res.x += c.x; res.y += c.y; }
            *p = res;
        }
        if (r1 < n_rows) {
            float2* p = (float2*)&out[(size_t)r1 * D + j * 8 + lcol2];
            float2 res;
            res.x = scv.x * (acc[j][2] - mean1) * inv1 + ofv.x;
            res.y = scv.y * (acc[j][3] - mean1) * inv1 + ofv.y;
            if (accumulate) { float2 c = *p; res.x += c.x; res.y += c.y; }
            *p = res;
        }
    }
}

// ---------------------------------------------------------------------------
extern "C" void kernel_launch(void* const* d_in, const int* in_sizes, int n_in,
                              void* d_out, int out_size) {
    const float* vecs = (const float*)d_in[0];
    const float* vals = (const float*)d_in[1];
    const int*   row  = (const int*)d_in[2];
    const int*   col  = (const int*)d_in[3];
    const float* W0 = (const float*)d_in[4];
    const float* b0 = (const float*)d_in[5];
    const float* off0 = (const float*)d_in[6];
    const float* sc0  = (const float*)d_in[7];
    const float* W1 = (const float*)d_in[8];
    const float* b1 = (const float*)d_in[9];
    const float* off1 = (const float*)d_in[10];
    const float* sc1  = (const float*)d_in[11];
    const float* W2 = (const float*)d_in[12];
    const float* b2 = (const float*)d_in[13];
    const float* off2 = (const float*)d_in[14];
    const float* sc2  = (const float*)d_in[15];
    float* out = (float*)d_out;

    const int n_edges = in_sizes[1];
    const int n_rows  = in_sizes[0] / D;

    float *hop1, *hop2, *cval;
    int *cnt, *rs, *cursor, *bsum, *ccol;
    __nv_bfloat16 *wth, *wtl;
    cudaGetSymbolAddress((void**)&hop1,   g_hop1);
    cudaGetSymbolAddress((void**)&hop2,   g_hop2);
    cudaGetSymbolAddress((void**)&cnt,    g_cnt);
    cudaGetSymbolAddress((void**)&rs,     g_rs);
    cudaGetSymbolAddress((void**)&cursor, g_cursor);
    cudaGetSymbolAddress((void**)&bsum,   g_bsum);
    cudaGetSymbolAddress((void**)&ccol,   g_ccol);
    cudaGetSymbolAddress((void**)&cval,   g_cval);
    cudaGetSymbolAddress((void**)&wth,    g_wt_hi);
    cudaGetSymbolAddress((void**)&wtl,    g_wt_lo);

    cudaFuncSetAttribute(gemm_mma_kernel,
                         cudaFuncAttributeMaxDynamicSharedMemorySize, TC_SMEM);

    // ---- W transpose + split (x3) ----
    wsplit_kernel<<<64, 256>>>(W0, wth + 0 * D * D, wtl + 0 * D * D);
    wsplit_kernel<<<64, 256>>>(W1, wth + 1 * D * D, wtl + 1 * D * D);
    wsplit_kernel<<<64, 256>>>(W2, wth + 2 * D * D, wtl + 2 * D * D);

    // ---- CSR build ----
    cudaMemsetAsync(cnt, 0, (size_t)n_rows * sizeof(int));
    const int eb = (n_edges + 255) / 256;
    hist_kernel<<<eb, 256>>>(row, n_edges, cnt);
    const int nb = (n_rows + SCAN_BLK - 1) / SCAN_BLK;
    scan_block_kernel<<<nb, SCAN_BLK>>>(cnt, rs, bsum, n_rows);
    scan_bsum_kernel<<<1, 1024>>>(bsum, nb);
    scan_add_kernel<<<(n_rows + 256) / 256, 256>>>(rs, bsum, cursor, n_rows, n_edges);
    scatter_kernel<<<eb, 256>>>(row, col, vals, n_edges, cursor, ccol, cval);

    // ---- 2-hop gather SpMM ----
    const int gw_blocks = (n_rows * 32 + 255) / 256;
    spmm_gather_kernel<<<gw_blocks, 256>>>(vecs, hop1, rs, ccol, cval, n_rows);
    spmm_gather_kernel<<<gw_blocks, 256>>>(hop1, hop2, rs, ccol, cval, n_rows);

    // ---- 3 mma.sync GEMM+norm ----
    const int gemm_blocks = (n_rows + 127) / 128;
    gemm_mma_kernel<<<gemm_blocks, 256, TC_SMEM>>>(vecs, wth + 0 * D * D, wtl + 0 * D * D,
                                                   b0, off0, sc0, out, n_rows, 0);
    gemm_mma_kernel<<<gemm_blocks, 256, TC_SMEM>>>(hop1, wth + 1 * D * D, wtl + 1 * D * D,
                                                   b1, off1, sc1, out, n_rows, 1);
    gemm_mma_kernel<<<gemm_blocks, 256, TC_SMEM>>>(hop2, wth + 2 * D * D, wtl + 2 * D * D,
                                                   b2, off2, sc2, out, n_rows, 1);
}

// round 6
// speedup vs baseline: 1.8012x; 1.8012x over previous
#include <cuda_runtime.h>
#include <cuda_bf16.h>
#include <cstdint>

#define D 128
#define MAX_N 100000
#define MAX_E 1600000
#define SCAN_BLK 512
#define KS 136                      // padded smem row stride (bf16 elems)

// ---------------- device-global scratch (allocation-free rule) ----------------
__device__ float g_hop1[(size_t)MAX_N * D];
__device__ float g_hop2[(size_t)MAX_N * D];
__device__ int   g_cnt[MAX_N];
__device__ int   g_rs[MAX_N + 1];
__device__ int   g_cursor[MAX_N];
__device__ int   g_bsum[1024];
__device__ int   g_ccol[MAX_E];
__device__ float g_cval[MAX_E];
__device__ __nv_bfloat16 g_wt_hi[3][D * D];   // W^T split, hi part  (wt[n][k])
__device__ __nv_bfloat16 g_wt_lo[3][D * D];   // W^T split, lo part

__device__ __forceinline__ uint32_t smem_u32(const void* p) {
    uint32_t a;
    asm("{ .reg .u64 t; cvta.to.shared.u64 t, %1; cvt.u32.u64 %0, t; }" : "=r"(a) : "l"(p));
    return a;
}
__device__ __forceinline__ void ldsm4(uint32_t& r0, uint32_t& r1, uint32_t& r2,
                                      uint32_t& r3, uint32_t addr) {
    asm volatile("ldmatrix.sync.aligned.m8n8.x4.shared.b16 {%0,%1,%2,%3}, [%4];"
                 : "=r"(r0), "=r"(r1), "=r"(r2), "=r"(r3) : "r"(addr));
}
__device__ __forceinline__ void mma16816(float* c, uint32_t a0, uint32_t a1,
                                         uint32_t a2, uint32_t a3,
                                         uint32_t b0, uint32_t b1) {
    asm volatile("mma.sync.aligned.m16n8k16.row.col.f32.bf16.bf16.f32 "
                 "{%0,%1,%2,%3}, {%4,%5,%6,%7}, {%8,%9}, {%0,%1,%2,%3};"
                 : "+f"(c[0]), "+f"(c[1]), "+f"(c[2]), "+f"(c[3])
                 : "r"(a0), "r"(a1), "r"(a2), "r"(a3), "r"(b0), "r"(b1));
}
// split float2 -> packed bf16 hi + packed bf16 lo
__device__ __forceinline__ void split2(float2 p, uint32_t& hi, uint32_t& lo) {
    __nv_bfloat16 hx = __float2bfloat16(p.x);
    __nv_bfloat16 hy = __float2bfloat16(p.y);
    hi = ((uint32_t)__bfloat16_as_ushort(hy) << 16) | __bfloat16_as_ushort(hx);
    __nv_bfloat16 lx = __float2bfloat16(p.x - __bfloat162float(hx));
    __nv_bfloat16 ly = __float2bfloat16(p.y - __bfloat162float(hy));
    lo = ((uint32_t)__bfloat16_as_ushort(ly) << 16) | __bfloat16_as_ushort(lx);
}

// ---------------------------------------------------------------------------
// CSR construction (unchanged)
// ---------------------------------------------------------------------------
__global__ void hist_kernel(const int* __restrict__ row, int n_edges, int* __restrict__ cnt) {
    int e = blockIdx.x * blockDim.x + threadIdx.x;
    if (e < n_edges) atomicAdd(&cnt[row[e]], 1);
}
__global__ void scan_block_kernel(const int* __restrict__ cnt, int* __restrict__ rs,
                                  int* __restrict__ bsum, int n) {
    __shared__ int sh[SCAN_BLK];
    int i = blockIdx.x * SCAN_BLK + threadIdx.x;
    int v = (i < n) ? cnt[i] : 0;
    sh[threadIdx.x] = v;
    __syncthreads();
    #pragma unroll
    for (int o = 1; o < SCAN_BLK; o <<= 1) {
        int t = (threadIdx.x >= o) ? sh[threadIdx.x - o] : 0;
        __syncthreads();
        sh[threadIdx.x] += t;
        __syncthreads();
    }
    int incl = sh[threadIdx.x];
    if (i < n) rs[i] = incl - v;
    if (threadIdx.x == SCAN_BLK - 1) bsum[blockIdx.x] = incl;
}
__global__ void scan_bsum_kernel(int* __restrict__ bsum, int nb) {
    __shared__ int sh[1024];
    int v = (threadIdx.x < nb) ? bsum[threadIdx.x] : 0;
    sh[threadIdx.x] = v;
    __syncthreads();
    #pragma unroll
    for (int o = 1; o < 1024; o <<= 1) {
        int t = (threadIdx.x >= o) ? sh[threadIdx.x - o] : 0;
        __syncthreads();
        sh[threadIdx.x] += t;
        __syncthreads();
    }
    if (threadIdx.x < nb) bsum[threadIdx.x] = sh[threadIdx.x] - v;
}
__global__ void scan_add_kernel(int* __restrict__ rs, const int* __restrict__ bsum,
                                int* __restrict__ cursor, int n, int total) {
    int i = blockIdx.x * blockDim.x + threadIdx.x;
    if (i < n) {
        int v = rs[i] + bsum[i >> 9];
        rs[i] = v;
        cursor[i] = v;
    }
    if (i == n) rs[n] = total;
}
__global__ void scatter_kernel(const int* __restrict__ row, const int* __restrict__ col,
                               const float* __restrict__ vals, int n_edges,
                               int* __restrict__ cursor, int* __restrict__ ccol,
                               float* __restrict__ cval) {
    int e = blockIdx.x * blockDim.x + threadIdx.x;
    if (e >= n_edges) return;
    int r = row[e];
    int p = atomicAdd(&cursor[r], 1);
    ccol[p] = col[e];
    cval[p] = vals[e];
}

// ---------------------------------------------------------------------------
// Gather SpMM (unchanged)
// ---------------------------------------------------------------------------
__global__ void __launch_bounds__(256)
spmm_gather_kernel(const float* __restrict__ x, float* __restrict__ y,
                   const int* __restrict__ rs, const int* __restrict__ ccol,
                   const float* __restrict__ cval, int n_rows) {
    int w    = (blockIdx.x * blockDim.x + threadIdx.x) >> 5;
    int lane = threadIdx.x & 31;
    if (w >= n_rows) return;
    int s = __ldg(&rs[w]);
    int e = __ldg(&rs[w + 1]);
    float4 acc = make_float4(0.f, 0.f, 0.f, 0.f);
    int j = s;
    for (; j + 3 < e; j += 4) {
        int   c0 = __ldg(&ccol[j]),     c1 = __ldg(&ccol[j + 1]);
        int   c2 = __ldg(&ccol[j + 2]), c3 = __ldg(&ccol[j + 3]);
        float v0 = __ldg(&cval[j]),     v1 = __ldg(&cval[j + 1]);
        float v2 = __ldg(&cval[j + 2]), v3 = __ldg(&cval[j + 3]);
        float4 x0 = ((const float4*)x)[(size_t)c0 * 32 + lane];
        float4 x1 = ((const float4*)x)[(size_t)c1 * 32 + lane];
        float4 x2 = ((const float4*)x)[(size_t)c2 * 32 + lane];
        float4 x3 = ((const float4*)x)[(size_t)c3 * 32 + lane];
        acc.x = fmaf(v0, x0.x, fmaf(v1, x1.x, fmaf(v2, x2.x, fmaf(v3, x3.x, acc.x))));
        acc.y = fmaf(v0, x0.y, fmaf(v1, x1.y, fmaf(v2, x2.y, fmaf(v3, x3.y, acc.y))));
        acc.z = fmaf(v0, x0.z, fmaf(v1, x1.z, fmaf(v2, x2.z, fmaf(v3, x3.z, acc.z))));
        acc.w = fmaf(v0, x0.w, fmaf(v1, x1.w, fmaf(v2, x2.w, fmaf(v3, x3.w, acc.w))));
    }
    for (; j < e; j++) {
        int   c = __ldg(&ccol[j]);
        float v = __ldg(&cval[j]);
        float4 xv = ((const float4*)x)[(size_t)c * 32 + lane];
        acc.x = fmaf(v, xv.x, acc.x);
        acc.y = fmaf(v, xv.y, acc.y);
        acc.z = fmaf(v, xv.z, acc.z);
        acc.w = fmaf(v, xv.w, acc.w);
    }
    ((float4*)y)[(size_t)w * 32 + lane] = acc;
}

// ---------------------------------------------------------------------------
// W transpose + bf16 hi/lo split: WT_hi[n][k] + WT_lo[n][k] = W[k][n]
// ---------------------------------------------------------------------------
__global__ void wsplit_kernel(const float* __restrict__ W,
                              __nv_bfloat16* __restrict__ wt_hi,
                              __nv_bfloat16* __restrict__ wt_lo) {
    int idx = blockIdx.x * blockDim.x + threadIdx.x;   // 0..16383
    int k = idx >> 7, n = idx & 127;
    float a = W[idx];
    __nv_bfloat16 h = __float2bfloat16(a);
    float res = a - __bfloat162float(h);
    wt_hi[n * D + k] = h;
    wt_lo[n * D + k] = __float2bfloat16(res);
}

// ---------------------------------------------------------------------------
// mma.sync bf16 3-pass-split GEMM (128x128 tile) + bias + relu + row-norm.
// B (hi/lo) staged in smem; A fragments loaded straight from global fp32 and
// split in registers. A loads for step k+1 prefetched during step k; B ldsm
// double-buffered across the j loop. 2 CTAs/SM.
// ---------------------------------------------------------------------------
#define TC_SMEM (2 * 128 * KS * 2)           // 69632 bytes (Bh + Bl only)

__global__ void __launch_bounds__(256, 2)
gemm_mma_kernel(const float* __restrict__ V,
                const __nv_bfloat16* __restrict__ wt_hi,
                const __nv_bfloat16* __restrict__ wt_lo,
                const float* __restrict__ b,
                const float* __restrict__ off,
                const float* __restrict__ sc,
                float* __restrict__ out,
                int n_rows, int accumulate) {
    extern __shared__ __nv_bfloat16 sm[];
    __nv_bfloat16* Bh = sm;
    __nv_bfloat16* Bl = Bh + 128 * KS;

    const int tid  = threadIdx.x;
    const int wid  = tid >> 5;
    const int lane = tid & 31;
    const int row0 = blockIdx.x * 128;

    // ---- stage B (pre-split W^T) ----
    const uint2* bhg = (const uint2*)wt_hi;
    const uint2* blg = (const uint2*)wt_lo;
    #pragma unroll
    for (int i = 0; i < 16; i++) {
        int idx = tid + i * 256;                 // 0..4095
        int r = idx >> 5;
        int c4 = (idx & 31) << 2;
        *(uint2*)&Bh[r * KS + c4] = __ldg(&bhg[idx]);
        *(uint2*)&Bl[r * KS + c4] = __ldg(&blg[idx]);
    }

    // ---- per-lane A addressing (fragment layout of m16n8k16 row-major A) ----
    const int ar  = row0 + wid * 16 + (lane >> 2);   // rows lane/4 and +8
    const int ac  = (lane & 3) * 2;                  // col pair base
    const bool v0 = (ar < n_rows);
    const bool v1 = (ar + 8 < n_rows);
    const float* pr0 = V + (size_t)ar * D + ac;
    const float* pr1 = pr0 + (size_t)8 * D;
    const float2 z2 = make_float2(0.f, 0.f);

    float2 p00 = v0 ? *(const float2*)(pr0)     : z2;   // k0 rows, k-half 0
    float2 p01 = v0 ? *(const float2*)(pr0 + 8) : z2;   //            k-half 1
    float2 p10 = v1 ? *(const float2*)(pr1)     : z2;
    float2 p11 = v1 ? *(const float2*)(pr1 + 8) : z2;

    float acc[16][4];
    #pragma unroll
    for (int j = 0; j < 16; j++)
        #pragma unroll
        for (int q = 0; q < 4; q++) acc[j][q] = 0.f;

    __syncthreads();

    const uint32_t Bh_u = smem_u32(Bh), Bl_u = smem_u32(Bl);
    const int nb = (lane & 7) + ((lane >> 4) & 1) * 8;
    const int kb = ((lane >> 3) & 1) * 8;

    #pragma unroll
    for (int k0 = 0; k0 < 8; k0++) {
        // prefetch A for next k-step
        float2 n00, n01, n10, n11;
        if (k0 < 7) {
            const int koff = (k0 + 1) * 16;
            n00 = v0 ? *(const float2*)(pr0 + koff)     : z2;
            n01 = v0 ? *(const float2*)(pr0 + koff + 8) : z2;
            n10 = v1 ? *(const float2*)(pr1 + koff)     : z2;
            n11 = v1 ? *(const float2*)(pr1 + koff + 8) : z2;
        }

        // split current A into hi/lo fragments (a0,a1,a2,a3)
        uint32_t ah0, ah1, ah2, ah3, al0, al1, al2, al3;
        split2(p00, ah0, al0);
        split2(p10, ah1, al1);
        split2(p01, ah2, al2);
        split2(p11, ah3, al3);

        // B double-buffered j loop
        uint32_t bh[2][4], bl[2][4];
        {
            const uint32_t o0 = (uint32_t)((0 * 16 + nb) * KS + k0 * 16 + kb) * 2;
            ldsm4(bh[0][0], bh[0][1], bh[0][2], bh[0][3], Bh_u + o0);
            ldsm4(bl[0][0], bl[0][1], bl[0][2], bl[0][3], Bl_u + o0);
        }
        #pragma unroll
        for (int j = 0; j < 8; j++) {
            const int cur = j & 1, nxt = cur ^ 1;
            if (j < 7) {
                const uint32_t o = (uint32_t)(((j + 1) * 16 + nb) * KS + k0 * 16 + kb) * 2;
                ldsm4(bh[nxt][0], bh[nxt][1], bh[nxt][2], bh[nxt][3], Bh_u + o);
                ldsm4(bl[nxt][0], bl[nxt][1], bl[nxt][2], bl[nxt][3], Bl_u + o);
            }
            mma16816(acc[2 * j],     ah0, ah1, ah2, ah3, bh[cur][0], bh[cur][1]);
            mma16816(acc[2 * j + 1], ah0, ah1, ah2, ah3, bh[cur][2], bh[cur][3]);
            mma16816(acc[2 * j],     ah0, ah1, ah2, ah3, bl[cur][0], bl[cur][1]);
            mma16816(acc[2 * j + 1], ah0, ah1, ah2, ah3, bl[cur][2], bl[cur][3]);
            mma16816(acc[2 * j],     al0, al1, al2, al3, bh[cur][0], bh[cur][1]);
            mma16816(acc[2 * j + 1], al0, al1, al2, al3, bh[cur][2], bh[cur][3]);
        }

        p00 = n00; p01 = n01; p10 = n10; p11 = n11;
    }

    // ---- epilogue: bias+relu, row moments (4-lane reduce), affine, store ----
    const int lrow  = lane >> 2;
    const int lcol2 = (lane & 3) * 2;
    float s0 = 0.f, sq0 = 0.f, s1 = 0.f, sq1 = 0.f;
    #pragma unroll
    for (int j = 0; j < 16; j++) {
        float2 bb = *(const float2*)&b[j * 8 + lcol2];
        float x0 = fmaxf(acc[j][0] + bb.x, 0.f);
        float x1 = fmaxf(acc[j][1] + bb.y, 0.f);
        float x2 = fmaxf(acc[j][2] + bb.x, 0.f);
        float x3 = fmaxf(acc[j][3] + bb.y, 0.f);
        acc[j][0] = x0; acc[j][1] = x1; acc[j][2] = x2; acc[j][3] = x3;
        s0 += x0 + x1; sq0 += x0 * x0 + x1 * x1;
        s1 += x2 + x3; sq1 += x2 * x2 + x3 * x3;
    }
    #pragma unroll
    for (int o = 1; o <= 2; o <<= 1) {
        s0  += __shfl_xor_sync(0xffffffffu, s0,  o);
        sq0 += __shfl_xor_sync(0xffffffffu, sq0, o);
        s1  += __shfl_xor_sync(0xffffffffu, s1,  o);
        sq1 += __shfl_xor_sync(0xffffffffu, sq1, o);
    }
    const float inv_d = 1.0f / 128.0f;
    float mean0 = s0 * inv_d, var0 = sq0 * inv_d - mean0 * mean0;
    float mean1 = s1 * inv_d, var1 = sq1 * inv_d - mean1 * mean1;
    float inv0 = rsqrtf(var0 + 1e-9f);
    float inv1 = rsqrtf(var1 + 1e-9f);

    const int r0 = row0 + wid * 16 + lrow;
    const int r1 = r0 + 8;
    #pragma unroll
    for (int j = 0; j < 16; j++) {
        float2 scv = *(const float2*)&sc[j * 8 + lcol2];
        float2 ofv = *(const float2*)&off[j * 8 + lcol2];
        if (r0 < n_rows) {
            float2* p = (float2*)&out[(size_t)r0 * D + j * 8 + lcol2];
            float2 res;
            res.x = scv.x * (acc[j][0] - mean0) * inv0 + ofv.x;
            res.y = scv.y * (acc[j][1] - mean0) * inv0 + ofv.y;
            if (accumulate) { float2 c = *p; res.x += c.x; res.y += c.y; }
            *p = res;
        }
        if (r1 < n_rows) {
            float2* p = (float2*)&out[(size_t)r1 * D + j * 8 + lcol2];
            float2 res;
            res.x = scv.x * (acc[j][2] - mean1) * inv1 + ofv.x;
            res.y = scv.y * (acc[j][3] - mean1) * inv1 + ofv.y;
            if (accumulate) { float2 c = *p; res.x += c.x; res.y += c.y; }
            *p = res;
        }
    }
}

// ---------------------------------------------------------------------------
extern "C" void kernel_launch(void* const* d_in, const int* in_sizes, int n_in,
                              void* d_out, int out_size) {
    const float* vecs = (const float*)d_in[0];
    const float* vals = (const float*)d_in[1];
    const int*   row  = (const int*)d_in[2];
    const int*   col  = (const int*)d_in[3];
    const float* W0 = (const float*)d_in[4];
    const float* b0 = (const float*)d_in[5];
    const float* off0 = (const float*)d_in[6];
    const float* sc0  = (const float*)d_in[7];
    const float* W1 = (const float*)d_in[8];
    const float* b1 = (const float*)d_in[9];
    const float* off1 = (const float*)d_in[10];
    const float* sc1  = (const float*)d_in[11];
    const float* W2 = (const float*)d_in[12];
    const float* b2 = (const float*)d_in[13];
    const float* off2 = (const float*)d_in[14];
    const float* sc2  = (const float*)d_in[15];
    float* out = (float*)d_out;

    const int n_edges = in_sizes[1];
    const int n_rows  = in_sizes[0] / D;

    float *hop1, *hop2, *cval;
    int *cnt, *rs, *cursor, *bsum, *ccol;
    __nv_bfloat16 *wth, *wtl;
    cudaGetSymbolAddress((void**)&hop1,   g_hop1);
    cudaGetSymbolAddress((void**)&hop2,   g_hop2);
    cudaGetSymbolAddress((void**)&cnt,    g_cnt);
    cudaGetSymbolAddress((void**)&rs,     g_rs);
    cudaGetSymbolAddress((void**)&cursor, g_cursor);
    cudaGetSymbolAddress((void**)&bsum,   g_bsum);
    cudaGetSymbolAddress((void**)&ccol,   g_ccol);
    cudaGetSymbolAddress((void**)&cval,   g_cval);
    cudaGetSymbolAddress((void**)&wth,    g_wt_hi);
    cudaGetSymbolAddress((void**)&wtl,    g_wt_lo);

    cudaFuncSetAttribute(gemm_mma_kernel,
                         cudaFuncAttributeMaxDynamicSharedMemorySize, TC_SMEM);

    // ---- W transpose + split (x3) ----
    wsplit_kernel<<<64, 256>>>(W0, wth + 0 * D * D, wtl + 0 * D * D);
    wsplit_kernel<<<64, 256>>>(W1, wth + 1 * D * D, wtl + 1 * D * D);
    wsplit_kernel<<<64, 256>>>(W2, wth + 2 * D * D, wtl + 2 * D * D);

    // ---- CSR build ----
    cudaMemsetAsync(cnt, 0, (size_t)n_rows * sizeof(int));
    const int eb = (n_edges + 255) / 256;
    hist_kernel<<<eb, 256>>>(row, n_edges, cnt);
    const int nb = (n_rows + SCAN_BLK - 1) / SCAN_BLK;
    scan_block_kernel<<<nb, SCAN_BLK>>>(cnt, rs, bsum, n_rows);
    scan_bsum_kernel<<<1, 1024>>>(bsum, nb);
    scan_add_kernel<<<(n_rows + 256) / 256, 256>>>(rs, bsum, cursor, n_rows, n_edges);
    scatter_kernel<<<eb, 256>>>(row, col, vals, n_edges, cursor, ccol, cval);

    // ---- 2-hop gather SpMM ----
    const int gw_blocks = (n_rows * 32 + 255) / 256;
    spmm_gather_kernel<<<gw_blocks, 256>>>(vecs, hop1, rs, ccol, cval, n_rows);
    spmm_gather_kernel<<<gw_blocks, 256>>>(hop1, hop2, rs, ccol, cval, n_rows);

    // ---- 3 mma.sync GEMM+norm ----
    const int gemm_blocks = (n_rows + 127) / 128;
    gemm_mma_kernel<<<gemm_blocks, 256, TC_SMEM>>>(vecs, wth + 0 * D * D, wtl + 0 * D * D,
                                                   b0, off0, sc0, out, n_rows, 0);
    gemm_mma_kernel<<<gemm_blocks, 256, TC_SMEM>>>(hop1, wth + 1 * D * D, wtl + 1 * D * D,
                                                   b1, off1, sc1, out, n_rows, 1);
    gemm_mma_kernel<<<gemm_blocks, 256, TC_SMEM>>>(hop2, wth + 2 * D * D, wtl + 2 * D * D,
                                                   b2, off2, sc2, out, n_rows, 1);
}

// round 7
// speedup vs baseline: 1.8486x; 1.0264x over previous
#include <cuda_runtime.h>
#include <cuda_bf16.h>
#include <cstdint>

#define D 128
#define MAX_N 100000
#define MAX_E 1600000
#define SCAN_BLK 512
#define KS 136                      // padded smem row stride (bf16 elems)
#define GEMM_GRID 296               // 2 CTAs/SM persistent

// ---------------- device-global scratch (allocation-free rule) ----------------
__device__ float g_hop1[(size_t)MAX_N * D];
__device__ float g_hop2[(size_t)MAX_N * D];
__device__ int   g_cnt[MAX_N];
__device__ int   g_rs[MAX_N + 1];
__device__ int   g_cursor[MAX_N];
__device__ int   g_bsum[1024];
__device__ int   g_ccol[MAX_E];
__device__ float g_cval[MAX_E];
__device__ __nv_bfloat16 g_wt_hi[3][D * D];   // W^T split, hi part  (wt[n][k])
__device__ __nv_bfloat16 g_wt_lo[3][D * D];   // W^T split, lo part

__device__ __forceinline__ uint32_t smem_u32(const void* p) {
    uint32_t a;
    asm("{ .reg .u64 t; cvta.to.shared.u64 t, %1; cvt.u32.u64 %0, t; }" : "=r"(a) : "l"(p));
    return a;
}
__device__ __forceinline__ void ldsm4(uint32_t& r0, uint32_t& r1, uint32_t& r2,
                                      uint32_t& r3, uint32_t addr) {
    asm volatile("ldmatrix.sync.aligned.m8n8.x4.shared.b16 {%0,%1,%2,%3}, [%4];"
                 : "=r"(r0), "=r"(r1), "=r"(r2), "=r"(r3) : "r"(addr));
}
__device__ __forceinline__ void mma16816(float* c, uint32_t a0, uint32_t a1,
                                         uint32_t a2, uint32_t a3,
                                         uint32_t b0, uint32_t b1) {
    asm volatile("mma.sync.aligned.m16n8k16.row.col.f32.bf16.bf16.f32 "
                 "{%0,%1,%2,%3}, {%4,%5,%6,%7}, {%8,%9}, {%0,%1,%2,%3};"
                 : "+f"(c[0]), "+f"(c[1]), "+f"(c[2]), "+f"(c[3])
                 : "r"(a0), "r"(a1), "r"(a2), "r"(a3), "r"(b0), "r"(b1));
}
__device__ __forceinline__ void split2(float2 p, uint32_t& hi, uint32_t& lo) {
    __nv_bfloat16 hx = __float2bfloat16(p.x);
    __nv_bfloat16 hy = __float2bfloat16(p.y);
    hi = ((uint32_t)__bfloat16_as_ushort(hy) << 16) | __bfloat16_as_ushort(hx);
    __nv_bfloat16 lx = __float2bfloat16(p.x - __bfloat162float(hx));
    __nv_bfloat16 ly = __float2bfloat16(p.y - __bfloat162float(hy));
    lo = ((uint32_t)__bfloat16_as_ushort(ly) << 16) | __bfloat16_as_ushort(lx);
}
__device__ __forceinline__ void red_add_v2(float* addr, float x, float y) {
    asm volatile("red.global.add.v2.f32 [%0], {%1, %2};"
                 :: "l"(addr), "f"(x), "f"(y) : "memory");
}

// ---------------------------------------------------------------------------
// CSR construction
// ---------------------------------------------------------------------------
__global__ void hist_kernel(const int* __restrict__ row, int n_edges, int* __restrict__ cnt) {
    int e = blockIdx.x * blockDim.x + threadIdx.x;
    if (e < n_edges) atomicAdd(&cnt[row[e]], 1);
}
__global__ void scan_block_kernel(const int* __restrict__ cnt, int* __restrict__ rs,
                                  int* __restrict__ bsum, int n) {
    __shared__ int sh[SCAN_BLK];
    int i = blockIdx.x * SCAN_BLK + threadIdx.x;
    int v = (i < n) ? cnt[i] : 0;
    sh[threadIdx.x] = v;
    __syncthreads();
    #pragma unroll
    for (int o = 1; o < SCAN_BLK; o <<= 1) {
        int t = (threadIdx.x >= o) ? sh[threadIdx.x - o] : 0;
        __syncthreads();
        sh[threadIdx.x] += t;
        __syncthreads();
    }
    int incl = sh[threadIdx.x];
    if (i < n) rs[i] = incl - v;
    if (threadIdx.x == SCAN_BLK - 1) bsum[blockIdx.x] = incl;
}
__global__ void scan_bsum_kernel(int* __restrict__ bsum, int nb) {
    __shared__ int sh[1024];
    int v = (threadIdx.x < nb) ? bsum[threadIdx.x] : 0;
    sh[threadIdx.x] = v;
    __syncthreads();
    #pragma unroll
    for (int o = 1; o < 1024; o <<= 1) {
        int t = (threadIdx.x >= o) ? sh[threadIdx.x - o] : 0;
        __syncthreads();
        sh[threadIdx.x] += t;
        __syncthreads();
    }
    if (threadIdx.x < nb) bsum[threadIdx.x] = sh[threadIdx.x] - v;
}
__global__ void scan_add_kernel(int* __restrict__ rs, const int* __restrict__ bsum,
                                int* __restrict__ cursor, int n, int total) {
    int i = blockIdx.x * blockDim.x + threadIdx.x;
    if (i < n) {
        int v = rs[i] + bsum[i >> 9];
        rs[i] = v;
        cursor[i] = v;
    }
    if (i == n) rs[n] = total;
}
__global__ void scatter_kernel(const int* __restrict__ row, const int* __restrict__ col,
                               const float* __restrict__ vals, int n_edges,
                               int* __restrict__ cursor, int* __restrict__ ccol,
                               float* __restrict__ cval) {
    int e = blockIdx.x * blockDim.x + threadIdx.x;
    if (e >= n_edges) return;
    int r = row[e];
    int p = atomicAdd(&cursor[r], 1);
    ccol[p] = col[e];
    cval[p] = vals[e];
}

// ---------------------------------------------------------------------------
// Gather SpMM: one warp per row, unroll 8 for MLP
// ---------------------------------------------------------------------------
__global__ void __launch_bounds__(256)
spmm_gather_kernel(const float* __restrict__ x, float* __restrict__ y,
                   const int* __restrict__ rs, const int* __restrict__ ccol,
                   const float* __restrict__ cval, int n_rows) {
    int w    = (blockIdx.x * blockDim.x + threadIdx.x) >> 5;
    int lane = threadIdx.x & 31;
    if (w >= n_rows) return;
    int s = __ldg(&rs[w]);
    int e = __ldg(&rs[w + 1]);
    float4 acc = make_float4(0.f, 0.f, 0.f, 0.f);
    int j = s;
    for (; j + 7 < e; j += 8) {
        int   c[8]; float v[8]; float4 xv[8];
        #pragma unroll
        for (int q = 0; q < 8; q++) c[q] = __ldg(&ccol[j + q]);
        #pragma unroll
        for (int q = 0; q < 8; q++) v[q] = __ldg(&cval[j + q]);
        #pragma unroll
        for (int q = 0; q < 8; q++) xv[q] = ((const float4*)x)[(size_t)c[q] * 32 + lane];
        #pragma unroll
        for (int q = 0; q < 8; q++) {
            acc.x = fmaf(v[q], xv[q].x, acc.x);
            acc.y = fmaf(v[q], xv[q].y, acc.y);
            acc.z = fmaf(v[q], xv[q].z, acc.z);
            acc.w = fmaf(v[q], xv[q].w, acc.w);
        }
    }
    for (; j < e; j++) {
        int   c = __ldg(&ccol[j]);
        float v = __ldg(&cval[j]);
        float4 xv = ((const float4*)x)[(size_t)c * 32 + lane];
        acc.x = fmaf(v, xv.x, acc.x);
        acc.y = fmaf(v, xv.y, acc.y);
        acc.z = fmaf(v, xv.z, acc.z);
        acc.w = fmaf(v, xv.w, acc.w);
    }
    ((float4*)y)[(size_t)w * 32 + lane] = acc;
}

// ---------------------------------------------------------------------------
// W transpose + bf16 hi/lo split for all 3 W's in one launch
// ---------------------------------------------------------------------------
__global__ void wsplit_kernel(const float* __restrict__ W0,
                              const float* __restrict__ W1,
                              const float* __restrict__ W2,
                              __nv_bfloat16* __restrict__ wt_hi,
                              __nv_bfloat16* __restrict__ wt_lo) {
    int o   = blockIdx.x >> 6;                       // 0..2
    int idx = (blockIdx.x & 63) * 256 + threadIdx.x; // 0..16383
    const float* W = (o == 0) ? W0 : (o == 1) ? W1 : W2;
    int k = idx >> 7, n = idx & 127;
    float a = W[idx];
    __nv_bfloat16 h = __float2bfloat16(a);
    float res = a - __bfloat162float(h);
    wt_hi[o * D * D + n * D + k] = h;
    wt_lo[o * D * D + n * D + k] = __float2bfloat16(res);
}

// ---------------------------------------------------------------------------
// Persistent mma.sync bf16 3-pass-split GEMM + bias + relu + row-norm.
// grid = GEMM_GRID CTAs; each loops over 128-row tiles. B staged once.
// accumulate==0: plain store; else red.global.add (no read-back).
// ---------------------------------------------------------------------------
#define TC_SMEM (2 * 128 * KS * 2)           // 69632 bytes (Bh + Bl)

__global__ void __launch_bounds__(256, 2)
gemm_mma_kernel(const float* __restrict__ V,
                const __nv_bfloat16* __restrict__ wt_hi,
                const __nv_bfloat16* __restrict__ wt_lo,
                const float* __restrict__ b,
                const float* __restrict__ off,
                const float* __restrict__ sc,
                float* __restrict__ out,
                int n_rows, int n_tiles, int accumulate) {
    extern __shared__ __nv_bfloat16 sm[];
    __nv_bfloat16* Bh = sm;
    __nv_bfloat16* Bl = Bh + 128 * KS;

    const int tid  = threadIdx.x;
    const int wid  = tid >> 5;
    const int lane = tid & 31;

    // ---- stage B once ----
    const uint2* bhg = (const uint2*)wt_hi;
    const uint2* blg = (const uint2*)wt_lo;
    #pragma unroll
    for (int i = 0; i < 16; i++) {
        int idx = tid + i * 256;
        int r = idx >> 5;
        int c4 = (idx & 31) << 2;
        *(uint2*)&Bh[r * KS + c4] = __ldg(&bhg[idx]);
        *(uint2*)&Bl[r * KS + c4] = __ldg(&blg[idx]);
    }
    __syncthreads();

    const uint32_t Bh_u = smem_u32(Bh), Bl_u = smem_u32(Bl);
    const int nb = (lane & 7) + ((lane >> 4) & 1) * 8;
    const int kb = ((lane >> 3) & 1) * 8;
    const int lrow  = lane >> 2;
    const int lcol2 = (lane & 3) * 2;
    const float2 z2 = make_float2(0.f, 0.f);
    const float inv_d = 1.0f / 128.0f;

    // per-thread epilogue constants (same for every tile)
    float2 bb[16], scv[16], ofv[16];
    #pragma unroll
    for (int j = 0; j < 16; j++) {
        bb[j]  = *(const float2*)&b[j * 8 + lcol2];
        scv[j] = *(const float2*)&sc[j * 8 + lcol2];
        ofv[j] = *(const float2*)&off[j * 8 + lcol2];
    }

    for (int tile = blockIdx.x; tile < n_tiles; tile += GEMM_GRID) {
        const int row0 = tile * 128;
        const int ar = row0 + wid * 16 + (lane >> 2);
        const int ac = (lane & 3) * 2;
        const bool v0 = (ar < n_rows);
        const bool v1 = (ar + 8 < n_rows);
        const float* pr0 = V + (size_t)ar * D + ac;
        const float* pr1 = pr0 + (size_t)8 * D;

        float2 p00 = v0 ? *(const float2*)(pr0)     : z2;
        float2 p01 = v0 ? *(const float2*)(pr0 + 8) : z2;
        float2 p10 = v1 ? *(const float2*)(pr1)     : z2;
        float2 p11 = v1 ? *(const float2*)(pr1 + 8) : z2;

        float acc[16][4];
        #pragma unroll
        for (int j = 0; j < 16; j++)
            #pragma unroll
            for (int q = 0; q < 4; q++) acc[j][q] = 0.f;

        #pragma unroll
        for (int k0 = 0; k0 < 8; k0++) {
            float2 n00, n01, n10, n11;
            if (k0 < 7) {
                const int koff = (k0 + 1) * 16;
                n00 = v0 ? *(const float2*)(pr0 + koff)     : z2;
                n01 = v0 ? *(const float2*)(pr0 + koff + 8) : z2;
                n10 = v1 ? *(const float2*)(pr1 + koff)     : z2;
                n11 = v1 ? *(const float2*)(pr1 + koff + 8) : z2;
            }

            uint32_t ah0, ah1, ah2, ah3, al0, al1, al2, al3;
            split2(p00, ah0, al0);
            split2(p10, ah1, al1);
            split2(p01, ah2, al2);
            split2(p11, ah3, al3);

            uint32_t bh[2][4], bl[2][4];
            {
                const uint32_t o0 = (uint32_t)((0 * 16 + nb) * KS + k0 * 16 + kb) * 2;
                ldsm4(bh[0][0], bh[0][1], bh[0][2], bh[0][3], Bh_u + o0);
                ldsm4(bl[0][0], bl[0][1], bl[0][2], bl[0][3], Bl_u + o0);
            }
            #pragma unroll
            for (int j = 0; j < 8; j++) {
                const int cur = j & 1, nxt = cur ^ 1;
                if (j < 7) {
                    const uint32_t o = (uint32_t)(((j + 1) * 16 + nb) * KS + k0 * 16 + kb) * 2;
                    ldsm4(bh[nxt][0], bh[nxt][1], bh[nxt][2], bh[nxt][3], Bh_u + o);
                    ldsm4(bl[nxt][0], bl[nxt][1], bl[nxt][2], bl[nxt][3], Bl_u + o);
                }
                mma16816(acc[2 * j],     ah0, ah1, ah2, ah3, bh[cur][0], bh[cur][1]);
                mma16816(acc[2 * j + 1], ah0, ah1, ah2, ah3, bh[cur][2], bh[cur][3]);
                mma16816(acc[2 * j],     ah0, ah1, ah2, ah3, bl[cur][0], bl[cur][1]);
                mma16816(acc[2 * j + 1], ah0, ah1, ah2, ah3, bl[cur][2], bl[cur][3]);
                mma16816(acc[2 * j],     al0, al1, al2, al3, bh[cur][0], bh[cur][1]);
                mma16816(acc[2 * j + 1], al0, al1, al2, al3, bh[cur][2], bh[cur][3]);
            }

            p00 = n00; p01 = n01; p10 = n10; p11 = n11;
        }

        // ---- epilogue ----
        float s0 = 0.f, sq0 = 0.f, s1 = 0.f, sq1 = 0.f;
        #pragma unroll
        for (int j = 0; j < 16; j++) {
            float x0 = fmaxf(acc[j][0] + bb[j].x, 0.f);
            float x1 = fmaxf(acc[j][1] + bb[j].y, 0.f);
            float x2 = fmaxf(acc[j][2] + bb[j].x, 0.f);
            float x3 = fmaxf(acc[j][3] + bb[j].y, 0.f);
            acc[j][0] = x0; acc[j][1] = x1; acc[j][2] = x2; acc[j][3] = x3;
            s0 += x0 + x1; sq0 += x0 * x0 + x1 * x1;
            s1 += x2 + x3; sq1 += x2 * x2 + x3 * x3;
        }
        #pragma unroll
        for (int o = 1; o <= 2; o <<= 1) {
            s0  += __shfl_xor_sync(0xffffffffu, s0,  o);
            sq0 += __shfl_xor_sync(0xffffffffu, sq0, o);
            s1  += __shfl_xor_sync(0xffffffffu, s1,  o);
            sq1 += __shfl_xor_sync(0xffffffffu, sq1, o);
        }
        float mean0 = s0 * inv_d, var0 = sq0 * inv_d - mean0 * mean0;
        float mean1 = s1 * inv_d, var1 = sq1 * inv_d - mean1 * mean1;
        float inv0 = rsqrtf(var0 + 1e-9f);
        float inv1 = rsqrtf(var1 + 1e-9f);

        const int r0 = row0 + wid * 16 + lrow;
        const int r1 = r0 + 8;
        #pragma unroll
        for (int j = 0; j < 16; j++) {
            if (r0 < n_rows) {
                float* p = &out[(size_t)r0 * D + j * 8 + lcol2];
                float rx = scv[j].x * (acc[j][0] - mean0) * inv0 + ofv[j].x;
                float ry = scv[j].y * (acc[j][1] - mean0) * inv0 + ofv[j].y;
                if (accumulate) red_add_v2(p, rx, ry);
                else            *(float2*)p = make_float2(rx, ry);
            }
            if (r1 < n_rows) {
                float* p = &out[(size_t)r1 * D + j * 8 + lcol2];
                float rx = scv[j].x * (acc[j][2] - mean1) * inv1 + ofv[j].x;
                float ry = scv[j].y * (acc[j][3] - mean1) * inv1 + ofv[j].y;
                if (accumulate) red_add_v2(p, rx, ry);
                else            *(float2*)p = make_float2(rx, ry);
            }
        }
    }
}

// ---------------------------------------------------------------------------
extern "C" void kernel_launch(void* const* d_in, const int* in_sizes, int n_in,
                              void* d_out, int out_size) {
    const float* vecs = (const float*)d_in[0];
    const float* vals = (const float*)d_in[1];
    const int*   row  = (const int*)d_in[2];
    const int*   col  = (const int*)d_in[3];
    const float* W0 = (const float*)d_in[4];
    const float* b0 = (const float*)d_in[5];
    const float* off0 = (const float*)d_in[6];
    const float* sc0  = (const float*)d_in[7];
    const float* W1 = (const float*)d_in[8];
    const float* b1 = (const float*)d_in[9];
    const float* off1 = (const float*)d_in[10];
    const float* sc1  = (const float*)d_in[11];
    const float* W2 = (const float*)d_in[12];
    const float* b2 = (const float*)d_in[13];
    const float* off2 = (const float*)d_in[14];
    const float* sc2  = (const float*)d_in[15];
    float* out = (float*)d_out;

    const int n_edges = in_sizes[1];
    const int n_rows  = in_sizes[0] / D;

    float *hop1, *hop2, *cval;
    int *cnt, *rs, *cursor, *bsum, *ccol;
    __nv_bfloat16 *wth, *wtl;
    cudaGetSymbolAddress((void**)&hop1,   g_hop1);
    cudaGetSymbolAddress((void**)&hop2,   g_hop2);
    cudaGetSymbolAddress((void**)&cnt,    g_cnt);
    cudaGetSymbolAddress((void**)&rs,     g_rs);
    cudaGetSymbolAddress((void**)&cursor, g_cursor);
    cudaGetSymbolAddress((void**)&bsum,   g_bsum);
    cudaGetSymbolAddress((void**)&ccol,   g_ccol);
    cudaGetSymbolAddress((void**)&cval,   g_cval);
    cudaGetSymbolAddress((void**)&wth,    g_wt_hi);
    cudaGetSymbolAddress((void**)&wtl,    g_wt_lo);

    cudaFuncSetAttribute(gemm_mma_kernel,
                         cudaFuncAttributeMaxDynamicSharedMemorySize, TC_SMEM);

    // ---- W transpose + split (single launch) ----
    wsplit_kernel<<<192, 256>>>(W0, W1, W2, wth, wtl);

    // ---- CSR build ----
    cudaMemsetAsync(cnt, 0, (size_t)n_rows * sizeof(int));
    const int eb = (n_edges + 255) / 256;
    hist_kernel<<<eb, 256>>>(row, n_edges, cnt);
    const int nb = (n_rows + SCAN_BLK - 1) / SCAN_BLK;
    scan_block_kernel<<<nb, SCAN_BLK>>>(cnt, rs, bsum, n_rows);
    scan_bsum_kernel<<<1, 1024>>>(bsum, nb);
    scan_add_kernel<<<(n_rows + 256) / 256, 256>>>(rs, bsum, cursor, n_rows, n_edges);
    scatter_kernel<<<eb, 256>>>(row, col, vals, n_edges, cursor, ccol, cval);

    // ---- 2-hop gather SpMM ----
    const int gw_blocks = (n_rows * 32 + 255) / 256;
    spmm_gather_kernel<<<gw_blocks, 256>>>(vecs, hop1, rs, ccol, cval, n_rows);
    spmm_gather_kernel<<<gw_blocks, 256>>>(hop1, hop2, rs, ccol, cval, n_rows);

    // ---- 3 persistent mma.sync GEMM+norm ----
    const int n_tiles = (n_rows + 127) / 128;
    gemm_mma_kernel<<<GEMM_GRID, 256, TC_SMEM>>>(vecs, wth + 0 * D * D, wtl + 0 * D * D,
                                                 b0, off0, sc0, out, n_rows, n_tiles, 0);
    gemm_mma_kernel<<<GEMM_GRID, 256, TC_SMEM>>>(hop1, wth + 1 * D * D, wtl + 1 * D * D,
                                                 b1, off1, sc1, out, n_rows, n_tiles, 1);
    gemm_mma_kernel<<<GEMM_GRID, 256, TC_SMEM>>>(hop2, wth + 2 * D * D, wtl + 2 * D * D,
                                                 b2, off2, sc2, out, n_rows, n_tiles, 1);
}

// round 8
// speedup vs baseline: 1.9850x; 1.0738x over previous
#include <cuda_runtime.h>
#include <cuda_bf16.h>
#include <cstdint>

#define D 128
#define MAX_N 100000
#define MAX_E 1600000
#define SCAN_BLK 512
#define KS 136                      // padded smem row stride (bf16 elems)
#define GEMM_GRID 296               // 2 CTAs/SM persistent

// ---------------- device-global scratch (allocation-free rule) ----------------
__device__ float g_hop1[(size_t)MAX_N * D];
__device__ float g_hop2[(size_t)MAX_N * D];
__device__ int   g_cnt[MAX_N];
__device__ int   g_rs[MAX_N + 1];
__device__ int   g_cursor[MAX_N];
__device__ int   g_bsum[1024];
__device__ int   g_ccol[MAX_E];
__device__ float g_cval[MAX_E];
__device__ __nv_bfloat16 g_wt_hi[3][D * D];
__device__ __nv_bfloat16 g_wt_lo[3][D * D];

__device__ __forceinline__ uint32_t smem_u32(const void* p) {
    uint32_t a;
    asm("{ .reg .u64 t; cvta.to.shared.u64 t, %1; cvt.u32.u64 %0, t; }" : "=r"(a) : "l"(p));
    return a;
}
__device__ __forceinline__ void ldsm4(uint32_t& r0, uint32_t& r1, uint32_t& r2,
                                      uint32_t& r3, uint32_t addr) {
    asm volatile("ldmatrix.sync.aligned.m8n8.x4.shared.b16 {%0,%1,%2,%3}, [%4];"
                 : "=r"(r0), "=r"(r1), "=r"(r2), "=r"(r3) : "r"(addr));
}
__device__ __forceinline__ void mma16816(float* c, uint32_t a0, uint32_t a1,
                                         uint32_t a2, uint32_t a3,
                                         uint32_t b0, uint32_t b1) {
    asm volatile("mma.sync.aligned.m16n8k16.row.col.f32.bf16.bf16.f32 "
                 "{%0,%1,%2,%3}, {%4,%5,%6,%7}, {%8,%9}, {%0,%1,%2,%3};"
                 : "+f"(c[0]), "+f"(c[1]), "+f"(c[2]), "+f"(c[3])
                 : "r"(a0), "r"(a1), "r"(a2), "r"(a3), "r"(b0), "r"(b1));
}
__device__ __forceinline__ void split2(float2 p, uint32_t& hi, uint32_t& lo) {
    __nv_bfloat16 hx = __float2bfloat16(p.x);
    __nv_bfloat16 hy = __float2bfloat16(p.y);
    hi = ((uint32_t)__bfloat16_as_ushort(hy) << 16) | __bfloat16_as_ushort(hx);
    __nv_bfloat16 lx = __float2bfloat16(p.x - __bfloat162float(hx));
    __nv_bfloat16 ly = __float2bfloat16(p.y - __bfloat162float(hy));
    lo = ((uint32_t)__bfloat16_as_ushort(ly) << 16) | __bfloat16_as_ushort(lx);
}
__device__ __forceinline__ void red_add_v2(float* addr, float x, float y) {
    asm volatile("red.global.add.v2.f32 [%0], {%1, %2};"
                 :: "l"(addr), "f"(x), "f"(y) : "memory");
}

// ---------------------------------------------------------------------------
// CSR construction
// ---------------------------------------------------------------------------
__global__ void hist_kernel(const int* __restrict__ row, int n_edges, int* __restrict__ cnt) {
    int i = blockIdx.x * blockDim.x + threadIdx.x;
    int e0 = i * 4;
    if (e0 + 3 < n_edges) {
        int4 r = *(const int4*)(row + e0);
        atomicAdd(&cnt[r.x], 1);
        atomicAdd(&cnt[r.y], 1);
        atomicAdd(&cnt[r.z], 1);
        atomicAdd(&cnt[r.w], 1);
    } else {
        for (int e = e0; e < n_edges; e++) atomicAdd(&cnt[row[e]], 1);
    }
}
__global__ void scan_block_kernel(const int* __restrict__ cnt, int* __restrict__ rs,
                                  int* __restrict__ bsum, int n) {
    __shared__ int sh[SCAN_BLK];
    int i = blockIdx.x * SCAN_BLK + threadIdx.x;
    int v = (i < n) ? cnt[i] : 0;
    sh[threadIdx.x] = v;
    __syncthreads();
    #pragma unroll
    for (int o = 1; o < SCAN_BLK; o <<= 1) {
        int t = (threadIdx.x >= o) ? sh[threadIdx.x - o] : 0;
        __syncthreads();
        sh[threadIdx.x] += t;
        __syncthreads();
    }
    int incl = sh[threadIdx.x];
    if (i < n) rs[i] = incl - v;
    if (threadIdx.x == SCAN_BLK - 1) bsum[blockIdx.x] = incl;
}
// fused: every block re-scans bsum (nb <= 256), then applies prefix
__global__ void scan_add_fused(int* __restrict__ rs, const int* __restrict__ bsum,
                               int* __restrict__ cursor, int n, int total, int nb) {
    __shared__ int sh[256];
    int t = threadIdx.x;
    int v = (t < nb) ? bsum[t] : 0;
    sh[t] = v;
    __syncthreads();
    #pragma unroll
    for (int o = 1; o < 256; o <<= 1) {
        int tv = (t >= o) ? sh[t - o] : 0;
        __syncthreads();
        sh[t] += tv;
        __syncthreads();
    }
    int i = blockIdx.x * 256 + t;
    if (i < n) {
        int blk = i >> 9;                       // SCAN_BLK == 512
        int excl = sh[blk] - bsum[blk];
        int v2 = rs[i] + excl;
        rs[i] = v2;
        cursor[i] = v2;
    }
    if (i == n) rs[n] = total;
}
__global__ void scatter_kernel(const int* __restrict__ row, const int* __restrict__ col,
                               const float* __restrict__ vals, int n_edges,
                               int* __restrict__ cursor, int* __restrict__ ccol,
                               float* __restrict__ cval) {
    int e = blockIdx.x * blockDim.x + threadIdx.x;
    if (e >= n_edges) return;
    int r = row[e];
    int p = atomicAdd(&cursor[r], 1);
    ccol[p] = col[e];
    cval[p] = vals[e];
}

// ---------------------------------------------------------------------------
// Gather SpMM: one warp per row, unroll 8 for MLP
// ---------------------------------------------------------------------------
__global__ void __launch_bounds__(256)
spmm_gather_kernel(const float* __restrict__ x, float* __restrict__ y,
                   const int* __restrict__ rs, const int* __restrict__ ccol,
                   const float* __restrict__ cval, int n_rows) {
    int w    = (blockIdx.x * blockDim.x + threadIdx.x) >> 5;
    int lane = threadIdx.x & 31;
    if (w >= n_rows) return;
    int s = __ldg(&rs[w]);
    int e = __ldg(&rs[w + 1]);
    float4 acc = make_float4(0.f, 0.f, 0.f, 0.f);
    int j = s;
    for (; j + 7 < e; j += 8) {
        int   c[8]; float v[8]; float4 xv[8];
        #pragma unroll
        for (int q = 0; q < 8; q++) c[q] = __ldg(&ccol[j + q]);
        #pragma unroll
        for (int q = 0; q < 8; q++) v[q] = __ldg(&cval[j + q]);
        #pragma unroll
        for (int q = 0; q < 8; q++) xv[q] = ((const float4*)x)[(size_t)c[q] * 32 + lane];
        #pragma unroll
        for (int q = 0; q < 8; q++) {
            acc.x = fmaf(v[q], xv[q].x, acc.x);
            acc.y = fmaf(v[q], xv[q].y, acc.y);
            acc.z = fmaf(v[q], xv[q].z, acc.z);
            acc.w = fmaf(v[q], xv[q].w, acc.w);
        }
    }
    for (; j < e; j++) {
        int   c = __ldg(&ccol[j]);
        float v = __ldg(&cval[j]);
        float4 xv = ((const float4*)x)[(size_t)c * 32 + lane];
        acc.x = fmaf(v, xv.x, acc.x);
        acc.y = fmaf(v, xv.y, acc.y);
        acc.z = fmaf(v, xv.z, acc.z);
        acc.w = fmaf(v, xv.w, acc.w);
    }
    ((float4*)y)[(size_t)w * 32 + lane] = acc;
}

// ---------------------------------------------------------------------------
// W transpose + bf16 hi/lo split for all 3 W's in one launch
// ---------------------------------------------------------------------------
__global__ void wsplit_kernel(const float* __restrict__ W0,
                              const float* __restrict__ W1,
                              const float* __restrict__ W2,
                              __nv_bfloat16* __restrict__ wt_hi,
                              __nv_bfloat16* __restrict__ wt_lo) {
    int o   = blockIdx.x >> 6;
    int idx = (blockIdx.x & 63) * 256 + threadIdx.x;
    const float* W = (o == 0) ? W0 : (o == 1) ? W1 : W2;
    int k = idx >> 7, n = idx & 127;
    float a = W[idx];
    __nv_bfloat16 h = __float2bfloat16(a);
    float res = a - __bfloat162float(h);
    wt_hi[o * D * D + n * D + k] = h;
    wt_lo[o * D * D + n * D + k] = __float2bfloat16(res);
}

// ---------------------------------------------------------------------------
// Persistent mma.sync bf16 3-pass-split GEMM + bias + relu + row-norm.
// ---------------------------------------------------------------------------
#define TC_SMEM (2 * 128 * KS * 2)           // 69632 bytes (Bh + Bl)

__global__ void __launch_bounds__(256, 2)
gemm_mma_kernel(const float* __restrict__ V,
                const __nv_bfloat16* __restrict__ wt_hi,
                const __nv_bfloat16* __restrict__ wt_lo,
                const float* __restrict__ b,
                const float* __restrict__ off,
                const float* __restrict__ sc,
                float* __restrict__ out,
                int n_rows, int n_tiles, int accumulate) {
    extern __shared__ __nv_bfloat16 sm[];
    __nv_bfloat16* Bh = sm;
    __nv_bfloat16* Bl = Bh + 128 * KS;

    const int tid  = threadIdx.x;
    const int wid  = tid >> 5;
    const int lane = tid & 31;

    const uint2* bhg = (const uint2*)wt_hi;
    const uint2* blg = (const uint2*)wt_lo;
    #pragma unroll
    for (int i = 0; i < 16; i++) {
        int idx = tid + i * 256;
        int r = idx >> 5;
        int c4 = (idx & 31) << 2;
        *(uint2*)&Bh[r * KS + c4] = __ldg(&bhg[idx]);
        *(uint2*)&Bl[r * KS + c4] = __ldg(&blg[idx]);
    }
    __syncthreads();

    const uint32_t Bh_u = smem_u32(Bh), Bl_u = smem_u32(Bl);
    const int nb = (lane & 7) + ((lane >> 4) & 1) * 8;
    const int kb = ((lane >> 3) & 1) * 8;
    const int lrow  = lane >> 2;
    const int lcol2 = (lane & 3) * 2;
    const float2 z2 = make_float2(0.f, 0.f);
    const float inv_d = 1.0f / 128.0f;

    float2 bb[16], scv[16], ofv[16];
    #pragma unroll
    for (int j = 0; j < 16; j++) {
        bb[j]  = *(const float2*)&b[j * 8 + lcol2];
        scv[j] = *(const float2*)&sc[j * 8 + lcol2];
        ofv[j] = *(const float2*)&off[j * 8 + lcol2];
    }

    for (int tile = blockIdx.x; tile < n_tiles; tile += GEMM_GRID) {
        const int row0 = tile * 128;
        const int ar = row0 + wid * 16 + (lane >> 2);
        const int ac = (lane & 3) * 2;
        const bool v0 = (ar < n_rows);
        const bool v1 = (ar + 8 < n_rows);
        const float* pr0 = V + (size_t)ar * D + ac;
        const float* pr1 = pr0 + (size_t)8 * D;

        float2 p00 = v0 ? *(const float2*)(pr0)     : z2;
        float2 p01 = v0 ? *(const float2*)(pr0 + 8) : z2;
        float2 p10 = v1 ? *(const float2*)(pr1)     : z2;
        float2 p11 = v1 ? *(const float2*)(pr1 + 8) : z2;

        float acc[16][4];
        #pragma unroll
        for (int j = 0; j < 16; j++)
            #pragma unroll
            for (int q = 0; q < 4; q++) acc[j][q] = 0.f;

        #pragma unroll
        for (int k0 = 0; k0 < 8; k0++) {
            float2 n00, n01, n10, n11;
            if (k0 < 7) {
                const int koff = (k0 + 1) * 16;
                n00 = v0 ? *(const float2*)(pr0 + koff)     : z2;
                n01 = v0 ? *(const float2*)(pr0 + koff + 8) : z2;
                n10 = v1 ? *(const float2*)(pr1 + koff)     : z2;
                n11 = v1 ? *(const float2*)(pr1 + koff + 8) : z2;
            }

            uint32_t ah0, ah1, ah2, ah3, al0, al1, al2, al3;
            split2(p00, ah0, al0);
            split2(p10, ah1, al1);
            split2(p01, ah2, al2);
            split2(p11, ah3, al3);

            uint32_t bh[2][4], bl[2][4];
            {
                const uint32_t o0 = (uint32_t)((0 * 16 + nb) * KS + k0 * 16 + kb) * 2;
                ldsm4(bh[0][0], bh[0][1], bh[0][2], bh[0][3], Bh_u + o0);
                ldsm4(bl[0][0], bl[0][1], bl[0][2], bl[0][3], Bl_u + o0);
            }
            #pragma unroll
            for (int j = 0; j < 8; j++) {
                const int cur = j & 1, nxt = cur ^ 1;
                if (j < 7) {
                    const uint32_t o = (uint32_t)(((j + 1) * 16 + nb) * KS + k0 * 16 + kb) * 2;
                    ldsm4(bh[nxt][0], bh[nxt][1], bh[nxt][2], bh[nxt][3], Bh_u + o);
                    ldsm4(bl[nxt][0], bl[nxt][1], bl[nxt][2], bl[nxt][3], Bl_u + o);
                }
                mma16816(acc[2 * j],     ah0, ah1, ah2, ah3, bh[cur][0], bh[cur][1]);
                mma16816(acc[2 * j + 1], ah0, ah1, ah2, ah3, bh[cur][2], bh[cur][3]);
                mma16816(acc[2 * j],     ah0, ah1, ah2, ah3, bl[cur][0], bl[cur][1]);
                mma16816(acc[2 * j + 1], ah0, ah1, ah2, ah3, bl[cur][2], bl[cur][3]);
                mma16816(acc[2 * j],     al0, al1, al2, al3, bh[cur][0], bh[cur][1]);
                mma16816(acc[2 * j + 1], al0, al1, al2, al3, bh[cur][2], bh[cur][3]);
            }

            p00 = n00; p01 = n01; p10 = n10; p11 = n11;
        }

        float s0 = 0.f, sq0 = 0.f, s1 = 0.f, sq1 = 0.f;
        #pragma unroll
        for (int j = 0; j < 16; j++) {
            float x0 = fmaxf(acc[j][0] + bb[j].x, 0.f);
            float x1 = fmaxf(acc[j][1] + bb[j].y, 0.f);
            float x2 = fmaxf(acc[j][2] + bb[j].x, 0.f);
            float x3 = fmaxf(acc[j][3] + bb[j].y, 0.f);
            acc[j][0] = x0; acc[j][1] = x1; acc[j][2] = x2; acc[j][3] = x3;
            s0 += x0 + x1; sq0 += x0 * x0 + x1 * x1;
            s1 += x2 + x3; sq1 += x2 * x2 + x3 * x3;
        }
        #pragma unroll
        for (int o = 1; o <= 2; o <<= 1) {
            s0  += __shfl_xor_sync(0xffffffffu, s0,  o);
            sq0 += __shfl_xor_sync(0xffffffffu, sq0, o);
            s1  += __shfl_xor_sync(0xffffffffu, s1,  o);
            sq1 += __shfl_xor_sync(0xffffffffu, sq1, o);
        }
        float mean0 = s0 * inv_d, var0 = sq0 * inv_d - mean0 * mean0;
        float mean1 = s1 * inv_d, var1 = sq1 * inv_d - mean1 * mean1;
        float inv0 = rsqrtf(var0 + 1e-9f);
        float inv1 = rsqrtf(var1 + 1e-9f);

        const int r0 = row0 + wid * 16 + lrow;
        const int r1 = r0 + 8;
        #pragma unroll
        for (int j = 0; j < 16; j++) {
            if (r0 < n_rows) {
                float* p = &out[(size_t)r0 * D + j * 8 + lcol2];
                float rx = scv[j].x * (acc[j][0] - mean0) * inv0 + ofv[j].x;
                float ry = scv[j].y * (acc[j][1] - mean0) * inv0 + ofv[j].y;
                if (accumulate) red_add_v2(p, rx, ry);
                else            *(float2*)p = make_float2(rx, ry);
            }
            if (r1 < n_rows) {
                float* p = &out[(size_t)r1 * D + j * 8 + lcol2];
                float rx = scv[j].x * (acc[j][2] - mean1) * inv1 + ofv[j].x;
                float ry = scv[j].y * (acc[j][3] - mean1) * inv1 + ofv[j].y;
                if (accumulate) red_add_v2(p, rx, ry);
                else            *(float2*)p = make_float2(rx, ry);
            }
        }
    }
}

// ---------------------------------------------------------------------------
extern "C" void kernel_launch(void* const* d_in, const int* in_sizes, int n_in,
                              void* d_out, int out_size) {
    const float* vecs = (const float*)d_in[0];
    const float* vals = (const float*)d_in[1];
    const int*   row  = (const int*)d_in[2];
    const int*   col  = (const int*)d_in[3];
    const float* W0 = (const float*)d_in[4];
    const float* b0 = (const float*)d_in[5];
    const float* off0 = (const float*)d_in[6];
    const float* sc0  = (const float*)d_in[7];
    const float* W1 = (const float*)d_in[8];
    const float* b1 = (const float*)d_in[9];
    const float* off1 = (const float*)d_in[10];
    const float* sc1  = (const float*)d_in[11];
    const float* W2 = (const float*)d_in[12];
    const float* b2 = (const float*)d_in[13];
    const float* off2 = (const float*)d_in[14];
    const float* sc2  = (const float*)d_in[15];
    float* out = (float*)d_out;

    const int n_edges = in_sizes[1];
    const int n_rows  = in_sizes[0] / D;

    float *hop1, *hop2, *cval;
    int *cnt, *rs, *cursor, *bsum, *ccol;
    __nv_bfloat16 *wth, *wtl;
    cudaGetSymbolAddress((void**)&hop1,   g_hop1);
    cudaGetSymbolAddress((void**)&hop2,   g_hop2);
    cudaGetSymbolAddress((void**)&cnt,    g_cnt);
    cudaGetSymbolAddress((void**)&rs,     g_rs);
    cudaGetSymbolAddress((void**)&cursor, g_cursor);
    cudaGetSymbolAddress((void**)&bsum,   g_bsum);
    cudaGetSymbolAddress((void**)&ccol,   g_ccol);
    cudaGetSymbolAddress((void**)&cval,   g_cval);
    cudaGetSymbolAddress((void**)&wth,    g_wt_hi);
    cudaGetSymbolAddress((void**)&wtl,    g_wt_lo);

    cudaFuncSetAttribute(gemm_mma_kernel,
                         cudaFuncAttributeMaxDynamicSharedMemorySize, TC_SMEM);

    // one-time side streams + events (created on the uncaptured correctness call)
    static cudaStream_t s2 = nullptr, s3 = nullptr;
    static cudaEvent_t evF = nullptr, ev1, ev2, evG0, evG1, evG2;
    if (s2 == nullptr) {
        cudaStreamCreateWithFlags(&s2, cudaStreamNonBlocking);
        cudaStreamCreateWithFlags(&s3, cudaStreamNonBlocking);
        cudaEventCreateWithFlags(&evF,  cudaEventDisableTiming);
        cudaEventCreateWithFlags(&ev1,  cudaEventDisableTiming);
        cudaEventCreateWithFlags(&ev2,  cudaEventDisableTiming);
        cudaEventCreateWithFlags(&evG0, cudaEventDisableTiming);
        cudaEventCreateWithFlags(&evG1, cudaEventDisableTiming);
        cudaEventCreateWithFlags(&evG2, cudaEventDisableTiming);
    }

    const int n_tiles = (n_rows + 127) / 128;

    // ---- fork: s2 does wsplit + gemm0 concurrently with CSR+spmm1 ----
    cudaEventRecord(evF, 0);
    cudaStreamWaitEvent(s2, evF, 0);
    wsplit_kernel<<<192, 256, 0, s2>>>(W0, W1, W2, wth, wtl);
    gemm_mma_kernel<<<GEMM_GRID, 256, TC_SMEM, s2>>>(vecs, wth + 0 * D * D, wtl + 0 * D * D,
                                                     b0, off0, sc0, out, n_rows, n_tiles, 0);
    cudaEventRecord(evG0, s2);

    // ---- main chain: CSR build + both SpMM hops ----
    cudaMemsetAsync(cnt, 0, (size_t)n_rows * sizeof(int), 0);
    hist_kernel<<<(n_edges / 4 + 255) / 256, 256>>>(row, n_edges, cnt);
    const int nb = (n_rows + SCAN_BLK - 1) / SCAN_BLK;
    scan_block_kernel<<<nb, SCAN_BLK>>>(cnt, rs, bsum, n_rows);
    scan_add_fused<<<(n_rows + 256) / 256, 256>>>(rs, bsum, cursor, n_rows, n_edges, nb);
    scatter_kernel<<<(n_edges + 255) / 256, 256>>>(row, col, vals, n_edges, cursor, ccol, cval);

    const int gw_blocks = (n_rows * 32 + 255) / 256;
    spmm_gather_kernel<<<gw_blocks, 256>>>(vecs, hop1, rs, ccol, cval, n_rows);
    cudaEventRecord(ev1, 0);
    spmm_gather_kernel<<<gw_blocks, 256>>>(hop1, hop2, rs, ccol, cval, n_rows);
    cudaEventRecord(ev2, 0);

    // ---- s3: gemm1 overlaps spmm2 (needs hop1 + gemm0's store) ----
    cudaStreamWaitEvent(s3, ev1, 0);
    cudaStreamWaitEvent(s3, evG0, 0);
    gemm_mma_kernel<<<GEMM_GRID, 256, TC_SMEM, s3>>>(hop1, wth + 1 * D * D, wtl + 1 * D * D,
                                                     b1, off1, sc1, out, n_rows, n_tiles, 1);
    cudaEventRecord(evG1, s3);

    // ---- s2: gemm2 after spmm2 + gemm1 (keeps red.add order deterministic) ----
    cudaStreamWaitEvent(s2, ev2, 0);
    cudaStreamWaitEvent(s2, evG1, 0);
    gemm_mma_kernel<<<GEMM_GRID, 256, TC_SMEM, s2>>>(hop2, wth + 2 * D * D, wtl + 2 * D * D,
                                                     b2, off2, sc2, out, n_rows, n_tiles, 1);
    cudaEventRecord(evG2, s2);

    // ---- join back to the capture stream ----
    cudaStreamWaitEvent(0, evG2, 0);
}